// round 1
// baseline (speedup 1.0000x reference)
#include <cuda_runtime.h>
#include <math.h>
#include <stdint.h>

// Problem dims
#define T_TOK 4096
#define NS    4095        // T-1 steps
#define EDIM  512
#define HDIM  1024
#define G4H   4096        // 4*H
#define NCLS  1221

// Recurrence config
#define NBLK  128         // persistent CTAs (<= 148 SMs, all co-resident)
#define HPB   8           // H / NBLK h-indices per CTA
#define REC_T 256         // threads per recurrence CTA

// ---------------- device scratch (no allocations allowed) ----------------
__device__ float    g_xs[NS * (2 * EDIM)];          // [4095,1024] concat inputs
__device__ float    g_xg[(size_t)NS * G4H];         // [4095,4096] x gate preacts
__device__ float    g_hs[(size_t)NS * HDIM];        // [4095,1024] hidden outputs
__device__ float    g_hbuf[2][HDIM];                // double-buffered h state
__device__ unsigned g_flags[NBLK];                  // monotonic step counters
__device__ float    g_bias[G4H];                    // b_ih + b_hh

// ---------------- kernel 0: embed/concat + init ----------------
__global__ void prep_kernel(const int* __restrict__ x,
                            const float* __restrict__ emb,
                            const float* __restrict__ b_ih,
                            const float* __restrict__ b_hh) {
    int b = blockIdx.x;
    if (b < NS) {
        int tok  = x[b];
        int last = x[NS];
        const float* e0 = emb + (size_t)tok  * EDIM;
        const float* e1 = emb + (size_t)last * EDIM;
        float* dst = g_xs + (size_t)b * (2 * EDIM);
        for (int j = threadIdx.x; j < EDIM; j += blockDim.x) {
            dst[j]        = e0[j];
            dst[EDIM + j] = e1[j];
        }
    } else {
        // init block: bias sum, zero h0, zero flags
        for (int j = threadIdx.x; j < G4H; j += blockDim.x)
            g_bias[j] = b_ih[j] + b_hh[j];
        float* hb = &g_hbuf[0][0];
        for (int j = threadIdx.x; j < 2 * HDIM; j += blockDim.x)
            hb[j] = 0.0f;
        for (int j = threadIdx.x; j < NBLK; j += blockDim.x)
            g_flags[j] = 0u;
    }
}

// ---------------- generic SGEMM: C[m,n] = sum_k A[m,k]*B[n,k] + bias[n] ----
// A: [M,K] row-major, B: [N,K] row-major (i.e. C = A @ B^T), bias broadcast.
template <int BM, int BN, int BK, int TM, int TN, int NT>
__global__ void __launch_bounds__(NT)
sgemm_tn(const float* __restrict__ A, const float* __restrict__ B,
         const float* __restrict__ bias, float* __restrict__ C,
         int M, int N, int K) {
    __shared__ float As[BK][BM];
    __shared__ float Bs[BK][BN];

    const int m0 = blockIdx.y * BM;
    const int n0 = blockIdx.x * BN;
    const int tid = threadIdx.x;

    // loader mapping: BK=8 -> 2 float4 per row slot
    const int arow = tid / (BK / 4);
    const int acol = (tid % (BK / 4)) * 4;

    // compute mapping
    const int tx = tid % (BN / TN);
    const int ty = tid / (BN / TN);

    float acc[TM][TN];
#pragma unroll
    for (int i = 0; i < TM; i++)
#pragma unroll
        for (int j = 0; j < TN; j++) acc[i][j] = 0.0f;

    for (int k0 = 0; k0 < K; k0 += BK) {
        float4 av = make_float4(0.f, 0.f, 0.f, 0.f);
        if (m0 + arow < M)
            av = *(const float4*)(A + (size_t)(m0 + arow) * K + k0 + acol);
        As[acol + 0][arow] = av.x;
        As[acol + 1][arow] = av.y;
        As[acol + 2][arow] = av.z;
        As[acol + 3][arow] = av.w;

        float4 bv = make_float4(0.f, 0.f, 0.f, 0.f);
        if (n0 + arow < N)
            bv = *(const float4*)(B + (size_t)(n0 + arow) * K + k0 + acol);
        Bs[acol + 0][arow] = bv.x;
        Bs[acol + 1][arow] = bv.y;
        Bs[acol + 2][arow] = bv.z;
        Bs[acol + 3][arow] = bv.w;

        __syncthreads();

#pragma unroll
        for (int k = 0; k < BK; k++) {
            float ar[TM], br[TN];
#pragma unroll
            for (int i = 0; i < TM; i++) ar[i] = As[k][ty * TM + i];
#pragma unroll
            for (int j = 0; j < TN; j++) br[j] = Bs[k][tx * TN + j];
#pragma unroll
            for (int i = 0; i < TM; i++)
#pragma unroll
                for (int j = 0; j < TN; j++)
                    acc[i][j] = fmaf(ar[i], br[j], acc[i][j]);
        }
        __syncthreads();
    }

#pragma unroll
    for (int i = 0; i < TM; i++) {
        int m = m0 + ty * TM + i;
        if (m >= M) continue;
#pragma unroll
        for (int j = 0; j < TN; j++) {
            int n = n0 + tx * TN + j;
            if (n < N) C[(size_t)m * N + n] = acc[i][j] + bias[n];
        }
    }
}

// ---------------- persistent LSTM recurrence ----------------
// 128 CTAs x 256 threads. CTA b owns h-indices [8b, 8b+8): 32 rows of W_hh
// (8 per gate), kept entirely in registers (128 weights/thread).
// Cross-CTA step sync: monotonic flags + double-buffered h in global.
__global__ void __launch_bounds__(REC_T, 1)
lstm_rec(const float* __restrict__ Whh) {
    __shared__ float h_s[HDIM];
    __shared__ float red[32];
    __shared__ float xg_s[32];
    __shared__ float c_s[HPB];

    const int b = blockIdx.x;
    const int tid = threadIdx.x;
    const int base = b * HPB;
    const int w = tid >> 5;
    const int l = tid & 31;

    // Load this thread's weight slice: rows r = 4w..4w+3 (grouped i,f,g,o),
    // k-elements l, l+32, ..., l+992 (coalesced global loads).
    float wreg[4][32];
#pragma unroll
    for (int rr = 0; rr < 4; rr++) {
        int r = 4 * w + rr;                       // local row 0..31
        int grow = (r >> 3) * HDIM + base + (r & 7);
        const float* wp = Whh + (size_t)grow * HDIM;
#pragma unroll
        for (int i = 0; i < 32; i++) wreg[rr][i] = wp[l + 32 * i];
    }
    if (tid < HPB) c_s[tid] = 0.0f;

    volatile unsigned* vflags = g_flags;

    for (int t = 0; t < NS; t++) {
        // prefetch x_gates[t] slice into smem (non-spinning threads)
        if (tid >= 224) {
            int r = tid - 224;                    // 0..31
            xg_s[r] = __ldcg(&g_xg[(size_t)t * G4H + (r >> 3) * HDIM + base + (r & 7)]);
        }
        // wait until all CTAs finished step t-1
        if (t > 0 && tid < NBLK) {
            while (vflags[tid] < (unsigned)t) { }
        }
        __syncthreads();

        // stage h(t) into smem (L2 read, bypass possibly-stale L1)
        const float* hsrc = &g_hbuf[t & 1][0];
        for (int k = tid; k < HDIM; k += REC_T) h_s[k] = __ldcg(hsrc + k);
        __syncthreads();

        // 4 dot products per warp (rows 4w..4w+3) over H=1024
        float a0 = 0.f, a1 = 0.f, a2 = 0.f, a3 = 0.f;
#pragma unroll
        for (int i = 0; i < 32; i++) {
            float hv = h_s[l + 32 * i];
            a0 = fmaf(wreg[0][i], hv, a0);
            a1 = fmaf(wreg[1][i], hv, a1);
            a2 = fmaf(wreg[2][i], hv, a2);
            a3 = fmaf(wreg[3][i], hv, a3);
        }
#pragma unroll
        for (int off = 16; off; off >>= 1) {
            a0 += __shfl_down_sync(0xffffffffu, a0, off);
            a1 += __shfl_down_sync(0xffffffffu, a1, off);
            a2 += __shfl_down_sync(0xffffffffu, a2, off);
            a3 += __shfl_down_sync(0xffffffffu, a3, off);
        }
        if (l == 0) {
            red[4 * w + 0] = a0;
            red[4 * w + 1] = a1;
            red[4 * w + 2] = a2;
            red[4 * w + 3] = a3;
        }
        __syncthreads();

        // gate math + state update for the 8 owned h-indices
        if (tid < HPB) {
            int j = tid;
            float gi = red[j]      + xg_s[j];
            float gf = red[8 + j]  + xg_s[8 + j];
            float gg = red[16 + j] + xg_s[16 + j];
            float go = red[24 + j] + xg_s[24 + j];
            float iv = 1.0f / (1.0f + expf(-gi));
            float fv = 1.0f / (1.0f + expf(-gf));
            float gv = tanhf(gg);
            float ov = 1.0f / (1.0f + expf(-go));
            float c = fv * c_s[j] + iv * gv;
            c_s[j] = c;
            float hh = ov * tanhf(c);
            g_hbuf[(t + 1) & 1][base + j] = hh;
            g_hs[(size_t)t * HDIM + base + j] = hh;
            __threadfence();   // make h stores visible device-wide before flag
        }
        __syncthreads();
        if (tid == 0) vflags[b] = (unsigned)(t + 1);   // release step t
    }
}

// ---------------- launch ----------------
extern "C" void kernel_launch(void* const* d_in, const int* in_sizes, int n_in,
                              void* d_out, int out_size) {
    const int*   x     = (const int*)d_in[0];
    const float* emb   = (const float*)d_in[1];
    const float* W_ih  = (const float*)d_in[2];
    const float* W_hh  = (const float*)d_in[3];
    const float* b_ih  = (const float*)d_in[4];
    const float* b_hh  = (const float*)d_in[5];
    const float* W_out = (const float*)d_in[6];
    const float* b_out = (const float*)d_in[7];
    float* out = (float*)d_out;

    float *p_xs, *p_xg, *p_hs, *p_bias;
    cudaGetSymbolAddress((void**)&p_xs, g_xs);
    cudaGetSymbolAddress((void**)&p_xg, g_xg);
    cudaGetSymbolAddress((void**)&p_hs, g_hs);
    cudaGetSymbolAddress((void**)&p_bias, g_bias);

    // 0) embed + concat + init state/flags/bias
    prep_kernel<<<NS + 1, 256>>>(x, emb, b_ih, b_hh);

    // 1) x_gates = xs @ W_ih^T + (b_ih+b_hh)   [4095 x 4096]
    {
        dim3 grid(G4H / 128, (NS + 127) / 128);
        sgemm_tn<128, 128, 8, 8, 8, 256><<<grid, 256>>>(
            p_xs, W_ih, p_bias, p_xg, NS, G4H, 2 * EDIM);
    }

    // 2) serial LSTM scan (persistent cooperative kernel)
    lstm_rec<<<NBLK, REC_T>>>(W_hh);

    // 3) out = hs @ W_out^T + b_out   [4095 x 1221]
    {
        dim3 grid((NCLS + 127) / 128, (NS + 127) / 128);
        sgemm_tn<128, 128, 8, 8, 8, 256><<<grid, 256>>>(
            p_hs, W_out, b_out, out, NS, NCLS, HDIM);
    }
}

// round 5
// speedup vs baseline: 2.0819x; 2.0819x over previous
#include <cuda_runtime.h>
#include <math.h>
#include <stdint.h>

// Problem dims
#define T_TOK 4096
#define NS    4095        // T-1 steps
#define EDIM  512
#define HDIM  1024
#define G4H   4096        // 4*H
#define NCLS  1221

// Recurrence config
#define NBLK  128         // persistent CTAs (all co-resident on 148 SMs)
#define HPB   8           // H / NBLK h-indices per CTA
#define REC_T 256         // threads per recurrence CTA
#define FPAD  32          // flag padding: one flag per 128B L2 line

// ---------------- device scratch (no allocations allowed) ----------------
__device__ float    g_xs[NS * (2 * EDIM)];          // [4095,1024] concat inputs
__device__ float    g_xg[(size_t)NS * G4H];         // [4095,4096] x gate preacts
__device__ float    g_hs[(size_t)NS * HDIM];        // [4095,1024] hidden outputs
__device__ float    g_hbuf[2][HDIM];                // double-buffered h state
__device__ unsigned g_flags[NBLK * FPAD];           // padded monotonic counters
__device__ float    g_bias[G4H];                    // b_ih + b_hh

// ---------------- kernel 0: embed/concat + init ----------------
__global__ void prep_kernel(const int* __restrict__ x,
                            const float* __restrict__ emb,
                            const float* __restrict__ b_ih,
                            const float* __restrict__ b_hh) {
    int b = blockIdx.x;
    if (b < NS) {
        int tok  = x[b];
        int last = x[NS];
        const float* e0 = emb + (size_t)tok  * EDIM;
        const float* e1 = emb + (size_t)last * EDIM;
        float* dst = g_xs + (size_t)b * (2 * EDIM);
        for (int j = threadIdx.x; j < EDIM; j += blockDim.x) {
            dst[j]        = e0[j];
            dst[EDIM + j] = e1[j];
        }
    } else {
        // init block: bias sum, zero h0 (both parity rows), zero flags
        for (int j = threadIdx.x; j < G4H; j += blockDim.x)
            g_bias[j] = b_ih[j] + b_hh[j];
        float* hb = &g_hbuf[0][0];
        for (int j = threadIdx.x; j < 2 * HDIM; j += blockDim.x)
            hb[j] = 0.0f;
        for (int j = threadIdx.x; j < NBLK * FPAD; j += blockDim.x)
            g_flags[j] = 0u;
    }
}

// ---------------- generic SGEMM: C[m,n] = sum_k A[m,k]*B[n,k] + bias[n] ----
template <int BM, int BN, int BK, int TM, int TN, int NT>
__global__ void __launch_bounds__(NT)
sgemm_tn(const float* __restrict__ A, const float* __restrict__ B,
         const float* __restrict__ bias, float* __restrict__ C,
         int M, int N, int K) {
    __shared__ float As[BK][BM];
    __shared__ float Bs[BK][BN];

    const int m0 = blockIdx.y * BM;
    const int n0 = blockIdx.x * BN;
    const int tid = threadIdx.x;

    const int arow = tid / (BK / 4);
    const int acol = (tid % (BK / 4)) * 4;
    const int tx = tid % (BN / TN);
    const int ty = tid / (BN / TN);

    float acc[TM][TN];
#pragma unroll
    for (int i = 0; i < TM; i++)
#pragma unroll
        for (int j = 0; j < TN; j++) acc[i][j] = 0.0f;

    for (int k0 = 0; k0 < K; k0 += BK) {
        float4 av = make_float4(0.f, 0.f, 0.f, 0.f);
        if (m0 + arow < M)
            av = *(const float4*)(A + (size_t)(m0 + arow) * K + k0 + acol);
        As[acol + 0][arow] = av.x;
        As[acol + 1][arow] = av.y;
        As[acol + 2][arow] = av.z;
        As[acol + 3][arow] = av.w;

        float4 bv = make_float4(0.f, 0.f, 0.f, 0.f);
        if (n0 + arow < N)
            bv = *(const float4*)(B + (size_t)(n0 + arow) * K + k0 + acol);
        Bs[acol + 0][arow] = bv.x;
        Bs[acol + 1][arow] = bv.y;
        Bs[acol + 2][arow] = bv.z;
        Bs[acol + 3][arow] = bv.w;

        __syncthreads();

#pragma unroll
        for (int k = 0; k < BK; k++) {
            float ar[TM], br[TN];
#pragma unroll
            for (int i = 0; i < TM; i++) ar[i] = As[k][ty * TM + i];
#pragma unroll
            for (int j = 0; j < TN; j++) br[j] = Bs[k][tx * TN + j];
#pragma unroll
            for (int i = 0; i < TM; i++)
#pragma unroll
                for (int j = 0; j < TN; j++)
                    acc[i][j] = fmaf(ar[i], br[j], acc[i][j]);
        }
        __syncthreads();
    }

#pragma unroll
    for (int i = 0; i < TM; i++) {
        int m = m0 + ty * TM + i;
        if (m >= M) continue;
#pragma unroll
        for (int j = 0; j < TN; j++) {
            int n = n0 + tx * TN + j;
            if (n < N) C[(size_t)m * N + n] = acc[i][j] + bias[n];
        }
    }
}

// ---------------- persistent LSTM recurrence (R1 protocol, de-hotspotted) --
// CTA b owns h-indices [8b, 8b+8): 32 rows of W_hh in registers.
// Sync = R1's proven fence->barrier->flag generation counters, but flags are
// padded to one per 128B line and the spin is throttled with __nanosleep.
__global__ void __launch_bounds__(REC_T, 1)
lstm_rec(const float* __restrict__ Whh) {
    __shared__ float h_s[HDIM];
    __shared__ float red[32];
    __shared__ float xg_s[32];
    __shared__ float c_s[HPB];

    const int b = blockIdx.x;
    const int tid = threadIdx.x;
    const int base = b * HPB;
    const int w = tid >> 5;
    const int l = tid & 31;

    // Weight slice: rows r = 4w..4w+3 (gate = r>>3, idx = r&7),
    // lane l holds k-elements l, l+32, ..., l+992 (coalesced loads).
    float wreg[4][32];
#pragma unroll
    for (int rr = 0; rr < 4; rr++) {
        int r = 4 * w + rr;
        int grow = (r >> 3) * HDIM + base + (r & 7);
        const float* wp = Whh + (size_t)grow * HDIM;
#pragma unroll
        for (int i = 0; i < 32; i++) wreg[rr][i] = wp[l + 32 * i];
    }
    if (tid < HPB) c_s[tid] = 0.0f;

    // prefetch xg(0) into a register (warp 7)
    float xg_next = 0.0f;
    const int xr = tid - 224;             // 0..31 for warp 7
    if (tid >= 224)
        xg_next = __ldcg(&g_xg[(size_t)0 * G4H + (xr >> 3) * HDIM + base + (xr & 7)]);

    for (int t = 0; t < NS; t++) {
        // commit prefetched xg(t); issue prefetch of xg(t+1) (hides cold DRAM)
        if (tid >= 224) {
            xg_s[xr] = xg_next;
            if (t + 1 < NS)
                xg_next = __ldcg(&g_xg[(size_t)(t + 1) * G4H +
                                       (xr >> 3) * HDIM + base + (xr & 7)]);
        }

        // wait until all CTAs finished step t-1 (padded flags + backoff)
        if (t > 0 && tid < NBLK) {
            volatile unsigned* f = &g_flags[tid * FPAD];
            while (*f < (unsigned)t) __nanosleep(64);
        }
        __syncthreads();

        // stage h(t) into smem (L2 read, bypass L1)
        const float* hsrc = &g_hbuf[t & 1][0];
        for (int k = tid; k < HDIM; k += REC_T) h_s[k] = __ldcg(hsrc + k);
        __syncthreads();

        // 4 dot products per warp (rows 4w..4w+3) over H=1024
        float a0 = 0.f, a1 = 0.f, a2 = 0.f, a3 = 0.f;
#pragma unroll
        for (int i = 0; i < 32; i++) {
            float hv = h_s[l + 32 * i];
            a0 = fmaf(wreg[0][i], hv, a0);
            a1 = fmaf(wreg[1][i], hv, a1);
            a2 = fmaf(wreg[2][i], hv, a2);
            a3 = fmaf(wreg[3][i], hv, a3);
        }
#pragma unroll
        for (int off = 16; off; off >>= 1) {
            a0 += __shfl_down_sync(0xffffffffu, a0, off);
            a1 += __shfl_down_sync(0xffffffffu, a1, off);
            a2 += __shfl_down_sync(0xffffffffu, a2, off);
            a3 += __shfl_down_sync(0xffffffffu, a3, off);
        }
        if (l == 0) {
            red[4 * w + 0] = a0;
            red[4 * w + 1] = a1;
            red[4 * w + 2] = a2;
            red[4 * w + 3] = a3;
        }
        __syncthreads();

        // gate math + state update for the 8 owned h-indices (R1-proven)
        if (tid < HPB) {
            int j = tid;
            float gi = red[j]      + xg_s[j];
            float gf = red[8 + j]  + xg_s[8 + j];
            float gg = red[16 + j] + xg_s[16 + j];
            float go = red[24 + j] + xg_s[24 + j];
            float iv = 1.0f / (1.0f + expf(-gi));
            float fv = 1.0f / (1.0f + expf(-gf));
            float gv = tanhf(gg);
            float ov = 1.0f / (1.0f + expf(-go));
            float c = fv * c_s[j] + iv * gv;
            c_s[j] = c;
            float hh = ov * tanhf(c);
            g_hbuf[(t + 1) & 1][base + j] = hh;
            g_hs[(size_t)t * HDIM + base + j] = hh;
            __threadfence();   // make h stores visible device-wide before flag
        }
        __syncthreads();
        if (tid == 0)
            *(volatile unsigned*)&g_flags[b * FPAD] = (unsigned)(t + 1);
    }
}

// ---------------- launch ----------------
extern "C" void kernel_launch(void* const* d_in, const int* in_sizes, int n_in,
                              void* d_out, int out_size) {
    const int*   x     = (const int*)d_in[0];
    const float* emb   = (const float*)d_in[1];
    const float* W_ih  = (const float*)d_in[2];
    const float* W_hh  = (const float*)d_in[3];
    const float* b_ih  = (const float*)d_in[4];
    const float* b_hh  = (const float*)d_in[5];
    const float* W_out = (const float*)d_in[6];
    const float* b_out = (const float*)d_in[7];
    float* out = (float*)d_out;

    float *p_xs, *p_xg, *p_hs, *p_bias;
    cudaGetSymbolAddress((void**)&p_xs, g_xs);
    cudaGetSymbolAddress((void**)&p_xg, g_xg);
    cudaGetSymbolAddress((void**)&p_hs, g_hs);
    cudaGetSymbolAddress((void**)&p_bias, g_bias);

    // 0) embed + concat + init state/flags/bias
    prep_kernel<<<NS + 1, 256>>>(x, emb, b_ih, b_hh);

    // 1) x_gates = xs @ W_ih^T + (b_ih+b_hh)   [4095 x 4096]
    {
        dim3 grid(G4H / 128, (NS + 127) / 128);
        sgemm_tn<128, 128, 8, 8, 8, 256><<<grid, 256>>>(
            p_xs, W_ih, p_bias, p_xg, NS, G4H, 2 * EDIM);
    }

    // 2) serial LSTM scan (persistent cooperative kernel)
    lstm_rec<<<NBLK, REC_T>>>(W_hh);

    // 3) out = hs @ W_out^T + b_out   [4095 x 1221]
    {
        dim3 grid((NCLS + 127) / 128, (NS + 127) / 128);
        sgemm_tn<128, 128, 8, 8, 8, 256><<<grid, 256>>>(
            p_hs, W_out, b_out, out, NS, NCLS, HDIM);
    }
}

// round 7
// speedup vs baseline: 2.6182x; 1.2576x over previous
#include <cuda_runtime.h>
#include <math.h>
#include <stdint.h>

// Problem dims
#define T_TOK 4096
#define NS    4095        // T-1 steps
#define EDIM  512
#define HDIM  1024
#define G4H   4096        // 4*H
#define NCLS  1221

// Recurrence config
#define NBLK  128         // persistent CTAs (all co-resident on 148 SMs)
#define HPB   8           // H / NBLK h-indices per CTA
#define REC_T 256         // threads per recurrence CTA
#define FPAD  32          // flag padding: one flag per 128B L2 line

// ---------------- device scratch (no allocations allowed) ----------------
__device__ float    g_xs[NS * (2 * EDIM)];          // [4095,1024] concat inputs
__device__ float    g_xg[(size_t)NS * G4H];         // [4095,4096] x gate preacts
__device__ float    g_hs[(size_t)NS * HDIM];        // [4095,1024] hidden outputs
__device__ __align__(16) float g_hbuf[2][HDIM];     // double-buffered h state
__device__ unsigned g_flags[NBLK * FPAD];           // padded monotonic counters
__device__ float    g_bias[G4H];                    // b_ih + b_hh

// Acquire load: orders ALL subsequent loads (compiler via "memory" clobber,
// HW via .acquire) after the flag observation. This is the R6 bug fix.
__device__ __forceinline__ unsigned ld_acquire(const unsigned* p) {
    unsigned v;
    asm volatile("ld.acquire.gpu.global.u32 %0, [%1];"
                 : "=r"(v) : "l"(p) : "memory");
    return v;
}

// ---------------- kernel 0: embed/concat + init ----------------
__global__ void prep_kernel(const int* __restrict__ x,
                            const float* __restrict__ emb,
                            const float* __restrict__ b_ih,
                            const float* __restrict__ b_hh) {
    int b = blockIdx.x;
    if (b < NS) {
        int tok  = x[b];
        int last = x[NS];
        const float* e0 = emb + (size_t)tok  * EDIM;
        const float* e1 = emb + (size_t)last * EDIM;
        float* dst = g_xs + (size_t)b * (2 * EDIM);
        for (int j = threadIdx.x; j < EDIM; j += blockDim.x) {
            dst[j]        = e0[j];
            dst[EDIM + j] = e1[j];
        }
    } else {
        // init block: bias sum, zero h0 (both parity rows), zero flags
        for (int j = threadIdx.x; j < G4H; j += blockDim.x)
            g_bias[j] = b_ih[j] + b_hh[j];
        float* hb = &g_hbuf[0][0];
        for (int j = threadIdx.x; j < 2 * HDIM; j += blockDim.x)
            hb[j] = 0.0f;
        for (int j = threadIdx.x; j < NBLK * FPAD; j += blockDim.x)
            g_flags[j] = 0u;
    }
}

// ---------------- generic SGEMM: C[m,n] = sum_k A[m,k]*B[n,k] + bias[n] ----
template <int BM, int BN, int BK, int TM, int TN, int NT>
__global__ void __launch_bounds__(NT)
sgemm_tn(const float* __restrict__ A, const float* __restrict__ B,
         const float* __restrict__ bias, float* __restrict__ C,
         int M, int N, int K) {
    __shared__ float As[BK][BM];
    __shared__ float Bs[BK][BN];

    const int m0 = blockIdx.y * BM;
    const int n0 = blockIdx.x * BN;
    const int tid = threadIdx.x;

    const int arow = tid / (BK / 4);
    const int acol = (tid % (BK / 4)) * 4;
    const int tx = tid % (BN / TN);
    const int ty = tid / (BN / TN);

    float acc[TM][TN];
#pragma unroll
    for (int i = 0; i < TM; i++)
#pragma unroll
        for (int j = 0; j < TN; j++) acc[i][j] = 0.0f;

    for (int k0 = 0; k0 < K; k0 += BK) {
        float4 av = make_float4(0.f, 0.f, 0.f, 0.f);
        if (m0 + arow < M)
            av = *(const float4*)(A + (size_t)(m0 + arow) * K + k0 + acol);
        As[acol + 0][arow] = av.x;
        As[acol + 1][arow] = av.y;
        As[acol + 2][arow] = av.z;
        As[acol + 3][arow] = av.w;

        float4 bv = make_float4(0.f, 0.f, 0.f, 0.f);
        if (n0 + arow < N)
            bv = *(const float4*)(B + (size_t)(n0 + arow) * K + k0 + acol);
        Bs[acol + 0][arow] = bv.x;
        Bs[acol + 1][arow] = bv.y;
        Bs[acol + 2][arow] = bv.z;
        Bs[acol + 3][arow] = bv.w;

        __syncthreads();

#pragma unroll
        for (int k = 0; k < BK; k++) {
            float ar[TM], br[TN];
#pragma unroll
            for (int i = 0; i < TM; i++) ar[i] = As[k][ty * TM + i];
#pragma unroll
            for (int j = 0; j < TN; j++) br[j] = Bs[k][tx * TN + j];
#pragma unroll
            for (int i = 0; i < TM; i++)
#pragma unroll
                for (int j = 0; j < TN; j++)
                    acc[i][j] = fmaf(ar[i], br[j], acc[i][j]);
        }
        __syncthreads();
    }

#pragma unroll
    for (int i = 0; i < TM; i++) {
        int m = m0 + ty * TM + i;
        if (m >= M) continue;
#pragma unroll
        for (int j = 0; j < TN; j++) {
            int n = n0 + tx * TN + j;
            if (n < N) C[(size_t)m * N + n] = acc[i][j] + bias[n];
        }
    }
}

// ---------------- persistent LSTM recurrence (proven flag protocol) ----
// CTA b owns h-indices [8b, 8b+8): 32 rows of W_hh in registers.
// Per-thread fused poll+load: thread tid's h-slice (one float4) comes from
// CTA (tid>>1); it ACQUIRE-spins on that flag, then loads. 2 barriers/step.
__global__ void __launch_bounds__(REC_T, 1)
lstm_rec(const float* __restrict__ Whh) {
    __shared__ float4 h4_s[HDIM / 4];     // staged h(t)
    __shared__ float red[2][32];          // warp dot results (parity)
    __shared__ float xg_s[2][32];         // x-gate slice (parity)

    const int b = blockIdx.x;
    const int tid = threadIdx.x;
    const int base = b * HPB;
    const int w = tid >> 5;
    const int l = tid & 31;

    // Weight slice: rows r = 4w..4w+3 (gate = r>>3, idx = r&7),
    // lane l holds k-elements l, l+32, ..., l+992 (coalesced loads).
    float wreg[4][32];
#pragma unroll
    for (int rr = 0; rr < 4; rr++) {
        int r = 4 * w + rr;
        int grow = (r >> 3) * HDIM + base + (r & 7);
        const float* wp = Whh + (size_t)grow * HDIM;
#pragma unroll
        for (int i = 0; i < 32; i++) wreg[rr][i] = wp[l + 32 * i];
    }

    float c_reg = 0.0f;                   // cell state (warp 0, lanes 0..7)

    // prefetch xg(0) into a register (warp 7)
    float xg_next = 0.0f;
    const int xr = tid - 224;             // 0..31 for warp 7
    if (tid >= 224)
        xg_next = __ldcg(&g_xg[(size_t)0 * G4H + (xr >> 3) * HDIM + base + (xr & 7)]);

    // this thread's producer flag (CTA tid>>1 produces its float4 slice)
    const unsigned* myflag = &g_flags[(tid >> 1) * FPAD];

    for (int t = 0; t < NS; t++) {
        const int p = t & 1;

        // commit prefetched xg(t); issue prefetch of xg(t+1)
        if (tid >= 224) {
            xg_s[p][xr] = xg_next;
            if (t + 1 < NS)
                xg_next = __ldcg(&g_xg[(size_t)(t + 1) * G4H +
                                       (xr >> 3) * HDIM + base + (xr & 7)]);
        }

        // per-thread: ACQUIRE-wait for my producer CTA, then load my slice.
        // The acquire (+memory clobber) forbids hoisting the data load above
        // the poll, at both compiler and HW level.
        if (t > 0) {
            while (ld_acquire(myflag) < (unsigned)t) { }
        }
        h4_s[tid] = __ldcg(((const float4*)&g_hbuf[t & 1][0]) + tid);
        __syncthreads();                  // barrier #1: h_s fully staged

        // 4 dot products per warp (rows 4w..4w+3) over H=1024
        const float* h_s = (const float*)h4_s;
        float a0 = 0.f, a1 = 0.f, a2 = 0.f, a3 = 0.f;
#pragma unroll
        for (int i = 0; i < 32; i++) {
            float hv = h_s[l + 32 * i];
            a0 = fmaf(wreg[0][i], hv, a0);
            a1 = fmaf(wreg[1][i], hv, a1);
            a2 = fmaf(wreg[2][i], hv, a2);
            a3 = fmaf(wreg[3][i], hv, a3);
        }
#pragma unroll
        for (int off = 16; off; off >>= 1) {
            a0 += __shfl_down_sync(0xffffffffu, a0, off);
            a1 += __shfl_down_sync(0xffffffffu, a1, off);
            a2 += __shfl_down_sync(0xffffffffu, a2, off);
            a3 += __shfl_down_sync(0xffffffffu, a3, off);
        }
        if (l == 0) {
            red[p][4 * w + 0] = a0;
            red[p][4 * w + 1] = a1;
            red[p][4 * w + 2] = a2;
            red[p][4 * w + 3] = a3;
        }
        __syncthreads();                  // barrier #2: red complete

        // epilogue: warp 0, one activation per lane (accurate expf/tanhf)
        if (tid < 32) {
            float pre = red[p][tid] + xg_s[p][tid];
            float act = ((tid >> 3) == 2) ? tanhf(pre)
                                          : 1.0f / (1.0f + expf(-pre));
            int j = tid & 7;
            float iv = __shfl_sync(0xffffffffu, act, j);
            float fv = __shfl_sync(0xffffffffu, act, j + 8);
            float gv = __shfl_sync(0xffffffffu, act, j + 16);
            float ov = __shfl_sync(0xffffffffu, act, j + 24);
            float hh = 0.0f;
            if (tid < 8) {
                c_reg = fv * c_reg + iv * gv;
                hh = ov * tanhf(c_reg);
                __stcg(&g_hbuf[(t + 1) & 1][base + j], hh);
                __threadfence();          // release: h visible before flag
            }
            __syncwarp();
            if (tid == 0)
                *(volatile unsigned*)&g_flags[b * FPAD] = (unsigned)(t + 1);
            if (tid < 8)                  // history store off critical path
                g_hs[(size_t)t * HDIM + base + j] = hh;
        }
        // no 3rd barrier: red/xg_s parity-buffered; h4_s(t+1) writes happen
        // only after each thread's own acquire-poll for t+1 succeeds.
    }
}

// ---------------- launch ----------------
extern "C" void kernel_launch(void* const* d_in, const int* in_sizes, int n_in,
                              void* d_out, int out_size) {
    const int*   x     = (const int*)d_in[0];
    const float* emb   = (const float*)d_in[1];
    const float* W_ih  = (const float*)d_in[2];
    const float* W_hh  = (const float*)d_in[3];
    const float* b_ih  = (const float*)d_in[4];
    const float* b_hh  = (const float*)d_in[5];
    const float* W_out = (const float*)d_in[6];
    const float* b_out = (const float*)d_in[7];
    float* out = (float*)d_out;

    float *p_xs, *p_xg, *p_hs, *p_bias;
    cudaGetSymbolAddress((void**)&p_xs, g_xs);
    cudaGetSymbolAddress((void**)&p_xg, g_xg);
    cudaGetSymbolAddress((void**)&p_hs, g_hs);
    cudaGetSymbolAddress((void**)&p_bias, g_bias);

    // 0) embed + concat + init state/flags/bias
    prep_kernel<<<NS + 1, 256>>>(x, emb, b_ih, b_hh);

    // 1) x_gates = xs @ W_ih^T + (b_ih+b_hh)   [4095 x 4096]
    {
        dim3 grid(G4H / 128, (NS + 127) / 128);
        sgemm_tn<128, 128, 8, 8, 8, 256><<<grid, 256>>>(
            p_xs, W_ih, p_bias, p_xg, NS, G4H, 2 * EDIM);
    }

    // 2) serial LSTM scan (persistent cooperative kernel)
    lstm_rec<<<NBLK, REC_T>>>(W_hh);

    // 3) out = hs @ W_out^T + b_out   [4095 x 1221]
    {
        dim3 grid((NCLS + 127) / 128, (NS + 127) / 128);
        sgemm_tn<128, 128, 8, 8, 8, 256><<<grid, 256>>>(
            p_hs, W_out, b_out, out, NS, NCLS, HDIM);
    }
}